// round 4
// baseline (speedup 1.0000x reference)
#include <cuda_runtime.h>

// out[b,h,i,j] = scores[b,h,i,j] + sum_d q[b,h,i,d] * E[(j-i)+4096, d]
// B=2,H=16,S=2048,D=64, NUM_EMB=8192.
//
// Tiling: 128x128 (i,j) tile per CTA. Toeplitz structure => tile needs E rows
// [4096-127+(j0-i0), +255) : 255 contiguous rows, SMEM-resident. D=64 fully
// resident, so the mainloop runs entirely out of SMEM.
// 256 threads (16x16), 8x8 microtile with STRIDED mapping:
//   i = i0 + ty + 16*ii,  j = j0 + tx + 16*jj
// => local E row r = (tx-ty) + 16*(jj-ii) + 127 : consecutive across lanes
//    (conflict-free LDS) and constant-offset addressable (o*16 rows apart).
// Packed fp32 math: fma.rn.f32x2 accumulates even-d in lo half, odd-d in hi.

#define S_LEN 2048
#define TILE 128

__device__ __forceinline__ void ffma2(unsigned long long& acc,
                                      unsigned long long a,
                                      unsigned long long b) {
    asm volatile("fma.rn.f32x2 %0, %1, %2, %0;" : "+l"(acc) : "l"(a), "l"(b));
}

// SMEM: Qs[128][64] + Es[255][66]  (66-float pitch => bank = r + d2 mod 32,
// conflict-free for 17 consecutive r across the warp)
#define Q_ELEMS (128 * 64)
#define E_PITCH 66
#define E_ELEMS (255 * E_PITCH)
#define SMEM_BYTES ((Q_ELEMS + E_ELEMS) * 4)

__global__ __launch_bounds__(256, 1)
void relpos_kernel(const float* __restrict__ query,
                   const float* __restrict__ scores,
                   const float* __restrict__ rel,
                   float* __restrict__ out)
{
    extern __shared__ float smem[];
    float* Qs = smem;            // [128][64]
    float* Es = smem + Q_ELEMS;  // [255][66]

    const int tid = threadIdx.x;
    const int tx = tid & 15;
    const int ty = tid >> 4;
    const int bh = blockIdx.z;
    const int i0 = blockIdx.y * TILE;
    const int j0 = blockIdx.x * TILE;

    // ---- Load Q tile: rows i0 .. i0+127, 64 floats each (2048 float4) ----
    const float* qg = query + ((size_t)bh * S_LEN + i0) * 64;
    #pragma unroll
    for (int k = 0; k < 8; ++k) {
        int idx = tid + k * 256;              // 0..2047
        int row = idx >> 4;
        int c   = (idx & 15) << 2;
        float4 v = *(const float4*)(qg + row * 64 + c);
        *(float4*)(Qs + row * 64 + c) = v;
    }

    // ---- Load E tile: 255 contiguous rows starting at rBase ----
    // rBase in [2049, 4223+...], always within [0, 8192-255]: no bounds checks.
    const int rBase = 4096 - 127 + (j0 - i0);
    const float* eg = rel + (size_t)rBase * 64;
    #pragma unroll
    for (int k = 0; k < 16; ++k) {
        int idx = tid + k * 256;              // 0..4095, need < 4080
        if (idx < 255 * 16) {
            int row = idx >> 4;
            int c   = (idx & 15) << 2;
            float4 v = *(const float4*)(eg + row * 64 + c);
            float* dst = Es + row * E_PITCH + c;   // pitch 66: rows 8B-aligned
            *(float2*)(dst)     = make_float2(v.x, v.y);
            *(float2*)(dst + 2) = make_float2(v.z, v.w);
        }
    }
    __syncthreads();

    // ---- Mainloop: 64 f32x2 accumulators (even-d lo, odd-d hi) ----
    unsigned long long acc[8][8];
    #pragma unroll
    for (int a = 0; a < 8; ++a)
        #pragma unroll
        for (int b = 0; b < 8; ++b) acc[a][b] = 0ULL;

    const float* qbase = Qs + ty * 64;                 // + ii*16*64
    const float* ebase = Es + (tx - ty + 15) * E_PITCH; // + o*16*66

    #pragma unroll 2
    for (int d2 = 0; d2 < 32; ++d2) {
        unsigned long long q2[8];
        unsigned long long ev[15];
        #pragma unroll
        for (int ii = 0; ii < 8; ++ii)
            q2[ii] = *(const unsigned long long*)(qbase + ii * (16 * 64) + 2 * d2);
        #pragma unroll
        for (int o = 0; o < 15; ++o)
            ev[o] = *(const unsigned long long*)(ebase + o * (16 * E_PITCH) + 2 * d2);
        #pragma unroll
        for (int ii = 0; ii < 8; ++ii)
            #pragma unroll
            for (int jj = 0; jj < 8; ++jj)
                ffma2(acc[ii][jj], q2[ii], ev[jj - ii + 7]);
    }

    // ---- Epilogue: out = scores + (lo + hi) ----
    const size_t base = ((size_t)bh * S_LEN + i0) * S_LEN + j0;
    const float* sg = scores + base;
    float* og = out + base;
    #pragma unroll
    for (int ii = 0; ii < 8; ++ii) {
        const int ro = (ty + 16 * ii) * S_LEN;
        #pragma unroll
        for (int jj = 0; jj < 8; ++jj) {
            const int c = tx + 16 * jj;
            union { unsigned long long u; float2 f; } cv;
            cv.u = acc[ii][jj];
            og[ro + c] = sg[ro + c] + (cv.f.x + cv.f.y);
        }
    }
}

extern "C" void kernel_launch(void* const* d_in, const int* in_sizes, int n_in,
                              void* d_out, int out_size) {
    // Identify inputs robustly by element count.
    const float* query  = nullptr;  // 2*16*2048*64   = 4194304
    const float* scores = nullptr;  // 2*16*2048*2048 = 134217728
    const float* rel    = nullptr;  // 8192*64        = 524288
    for (int i = 0; i < n_in; ++i) {
        if (in_sizes[i] == 4194304)        query  = (const float*)d_in[i];
        else if (in_sizes[i] == 134217728) scores = (const float*)d_in[i];
        else if (in_sizes[i] == 524288)    rel    = (const float*)d_in[i];
    }

    cudaFuncSetAttribute(relpos_kernel,
                         cudaFuncAttributeMaxDynamicSharedMemorySize,
                         SMEM_BYTES);

    dim3 grid(S_LEN / TILE, S_LEN / TILE, 32);  // (16, 16, B*H)
    relpos_kernel<<<grid, 256, SMEM_BYTES>>>(query, scores, rel,
                                             (float*)d_out);
}

// round 6
// speedup vs baseline: 1.6385x; 1.6385x over previous
#include <cuda_runtime.h>
#include <cstdint>

// out[b,h,i,j] = scores[b,h,i,j] + sum_d q[b,h,i,d] * E[(j-i)+4096, d]
// B=2,H=16,S=2048,D=64.
//
// Per 128x128 (i,j) tile (Toeplitz): G[i,r] = Q(128x64) . E_rows(256x64)^T,
// where E_rows are 256 contiguous rel_emb rows; out j = r + i - 127.
// Portable tensor-core path: mma.sync.m16n8k8 tf32 (sm_80 PTX -> works on
// the plain sm_103 target this harness emits; tcgen05 is arch-gated OFF).
// Each of 8 warps owns one 16-row m-tile and computes ONLY the 18 8-wide
// n-tiles covering its diagonal band (1.125x necessary math, not 2x).
// Inputs rounded to tf32 via cvt.rna (RN, not truncation) when staged to SMEM.
// Epilogue: fragments -> SMEM sG[i][j] (diagonal reindex, scalar predicated
// STS), then fully coalesced float4 (scores + sG) -> out.
// sG aliases Q/E SMEM => 102KB/CTA => 2 CTAs/SM at 128 regs.

#define S_LEN 2048
#define QP 68            // Q SMEM pitch (floats): bank = 4*gid+tig, bijective
#define EP 68            // E SMEM pitch
#define GP 132           // sG pitch
#define SMEM_U32 (128 * QP + 256 * EP)     // 26112 words
#define SMEM_BYTES (SMEM_U32 * 4)          // 104448 (sG 128*132*4=67584 aliases)

__device__ __forceinline__ uint32_t f2tf32(float f) {
    uint32_t r;
    asm("cvt.rna.tf32.f32 %0, %1;" : "=r"(r) : "f"(f));
    return r;
}

__device__ __forceinline__ void mma_tf32(float* c,
                                         uint32_t a0, uint32_t a1,
                                         uint32_t a2, uint32_t a3,
                                         uint32_t b0, uint32_t b1) {
    asm volatile(
        "mma.sync.aligned.m16n8k8.row.col.f32.tf32.tf32.f32 "
        "{%0,%1,%2,%3}, {%4,%5,%6,%7}, {%8,%9}, {%0,%1,%2,%3};"
        : "+f"(c[0]), "+f"(c[1]), "+f"(c[2]), "+f"(c[3])
        : "r"(a0), "r"(a1), "r"(a2), "r"(a3), "r"(b0), "r"(b1));
}

__global__ __launch_bounds__(256, 2)
void relpos_mma(const float* __restrict__ query,
                const float* __restrict__ scores,
                const float* __restrict__ rel,
                float* __restrict__ out)
{
    extern __shared__ uint32_t smem[];
    uint32_t* Qs = smem;              // [128][QP] tf32 bits
    uint32_t* Es = smem + 128 * QP;   // [256][EP] tf32 bits

    const int tid  = threadIdx.x;
    const int wid  = tid >> 5;
    const int lane = tid & 31;
    const int gid  = lane >> 2;       // 0..7
    const int tig  = lane & 3;        // 0..3
    const int bh = blockIdx.z;
    const int i0 = blockIdx.y * 128;
    const int j0 = blockIdx.x * 128;

    // ---- Stage Q tile (128x64) to SMEM, rounding to tf32 (RN) ----
    const float* qg = query + ((size_t)bh * S_LEN + i0) * 64;
    #pragma unroll
    for (int k = 0; k < 8; ++k) {
        int idx = tid + k * 256;              // 2048 float4
        int row = idx >> 4;
        int c   = (idx & 15) << 2;
        float4 v = *(const float4*)(qg + row * 64 + c);
        uint32_t* d = Qs + row * QP + c;
        d[0] = f2tf32(v.x); d[1] = f2tf32(v.y);
        d[2] = f2tf32(v.z); d[3] = f2tf32(v.w);
    }
    // ---- Stage E tile: 256 contiguous rows from rBase (always in-bounds) ----
    const int rBase = 4096 - 127 + (j0 - i0);   // [2049, 5889]; +255 < 8192
    const float* eg = rel + (size_t)rBase * 64;
    #pragma unroll
    for (int k = 0; k < 16; ++k) {
        int idx = tid + k * 256;              // 4096 float4
        int row = idx >> 4;
        int c   = (idx & 15) << 2;
        float4 v = *(const float4*)(eg + row * 64 + c);
        uint32_t* d = Es + row * EP + c;
        d[0] = f2tf32(v.x); d[1] = f2tf32(v.y);
        d[2] = f2tf32(v.z); d[3] = f2tf32(v.w);
    }
    __syncthreads();

    // ---- Band mainloop: warp wid = m-tile (rows 16wid..16wid+15) ----
    // needed r in [112-16wid, 254-16wid] -> n-tiles n = (14-2wid)+t, t<18
    const int nBase = 14 - 2 * wid;
    float acc[18][4];
    #pragma unroll
    for (int t = 0; t < 18; ++t) {
        acc[t][0] = 0.f; acc[t][1] = 0.f; acc[t][2] = 0.f; acc[t][3] = 0.f;
    }

    const uint32_t* aP = Qs + (16 * wid + gid) * QP + tig;
    const uint32_t* bP = Es + (8 * nBase + gid) * EP + tig;

    #pragma unroll
    for (int k = 0; k < 8; ++k) {
        uint32_t a0 = aP[0];
        uint32_t a1 = aP[8 * QP];
        uint32_t a2 = aP[4];
        uint32_t a3 = aP[8 * QP + 4];
        #pragma unroll
        for (int t = 0; t < 18; ++t) {
            const uint32_t* bp = bP + t * (8 * EP);
            mma_tf32(acc[t], a0, a1, a2, a3, bp[0], bp[4]);
        }
        aP += 8;
        bP += 8;
    }

    __syncthreads();                 // all warps done reading Qs/Es
    float* sG = (float*)smem;        // alias: [128][GP], G[i][j]

    // ---- Scatter fragments diagonal-reindexed: j = r + i - 127 ----
    {
        const int iA = 16 * wid + gid;
        const int iB = iA + 8;
        #pragma unroll
        for (int t = 0; t < 18; ++t) {
            int r0 = 8 * (nBase + t) + 2 * tig;
            int jA = r0 + iA - 127;
            int jB = r0 + iB - 127;
            if ((unsigned)jA       < 128u) sG[iA * GP + jA]     = acc[t][0];
            if ((unsigned)(jA + 1) < 128u) sG[iA * GP + jA + 1] = acc[t][1];
            if ((unsigned)jB       < 128u) sG[iB * GP + jB]     = acc[t][2];
            if ((unsigned)(jB + 1) < 128u) sG[iB * GP + jB + 1] = acc[t][3];
        }
    }
    __syncthreads();

    // ---- Coalesced epilogue: out = scores + sG ----
    const size_t gbase = ((size_t)bh * S_LEN + i0) * S_LEN + j0;
    const int c4 = (tid & 31) << 2;
    #pragma unroll
    for (int k = 0; k < 16; ++k) {
        int il = (tid >> 5) + 8 * k;
        float4 s = *(const float4*)(scores + gbase + (size_t)il * S_LEN + c4);
        float4 g = *(const float4*)(sG + il * GP + c4);
        float4 o;
        o.x = s.x + g.x;
        o.y = s.y + g.y;
        o.z = s.z + g.z;
        o.w = s.w + g.w;
        *(float4*)(out + gbase + (size_t)il * S_LEN + c4) = o;
    }
}

extern "C" void kernel_launch(void* const* d_in, const int* in_sizes, int n_in,
                              void* d_out, int out_size) {
    const float* query  = nullptr;  // 2*16*2048*64   = 4194304
    const float* scores = nullptr;  // 2*16*2048*2048 = 134217728
    const float* rel    = nullptr;  // 8192*64        = 524288
    for (int i = 0; i < n_in; ++i) {
        if (in_sizes[i] == 4194304)        query  = (const float*)d_in[i];
        else if (in_sizes[i] == 134217728) scores = (const float*)d_in[i];
        else if (in_sizes[i] == 524288)    rel    = (const float*)d_in[i];
    }

    cudaFuncSetAttribute(relpos_mma,
                         cudaFuncAttributeMaxDynamicSharedMemorySize,
                         SMEM_BYTES);

    dim3 grid(S_LEN / 128, S_LEN / 128, 32);  // (16, 16, B*H)
    relpos_mma<<<grid, 256, SMEM_BYTES>>>(query, scores, rel, (float*)d_out);
}